// round 1
// baseline (speedup 1.0000x reference)
#include <cuda_runtime.h>

// HomographyNet: per-item truncated matrix exponential of C = sum_k v_k * B_k,
// B = fixed sl(3) basis =>
//   C = [ v4   v2   v0 ]
//       [ v3  -v4-v5 v1 ]
//       [ v6   v7   v5 ]
// H = sum_{i=0..9} C^i / i!
//
// Formulation: U_1 = C; U_i = U_{i-1} @ C; H = I + sum U_i * (1/i!)
// (same operator ordering as reference's A=(A/i)@C up to fp rounding).

__device__ __forceinline__ void expm3x3(const float vv[8], float H[9]) {
    const float c00 = vv[4], c01 = vv[2], c02 = vv[0];
    const float c10 = vv[3], c11 = -vv[4] - vv[5], c12 = vv[1];
    const float c20 = vv[6], c21 = vv[7], c22 = vv[5];

    // i = 1: U = C, H = I + C
    float u00 = c00, u01 = c01, u02 = c02;
    float u10 = c10, u11 = c11, u12 = c12;
    float u20 = c20, u21 = c21, u22 = c22;

    H[0] = 1.0f + c00; H[1] = c01;        H[2] = c02;
    H[3] = c10;        H[4] = 1.0f + c11; H[5] = c12;
    H[6] = c20;        H[7] = c21;        H[8] = 1.0f + c22;

    const float invf[10] = {
        0.0f, 1.0f, 0.5f, 1.0f / 6.0f, 1.0f / 24.0f, 1.0f / 120.0f,
        1.0f / 720.0f, 1.0f / 5040.0f, 1.0f / 40320.0f, 1.0f / 362880.0f
    };

#pragma unroll
    for (int i = 2; i <= 9; i++) {
        // U = U @ C
        float t00 = fmaf(u02, c20, fmaf(u01, c10, u00 * c00));
        float t01 = fmaf(u02, c21, fmaf(u01, c11, u00 * c01));
        float t02 = fmaf(u02, c22, fmaf(u01, c12, u00 * c02));
        float t10 = fmaf(u12, c20, fmaf(u11, c10, u10 * c00));
        float t11 = fmaf(u12, c21, fmaf(u11, c11, u10 * c01));
        float t12 = fmaf(u12, c22, fmaf(u11, c12, u10 * c02));
        float t20 = fmaf(u22, c20, fmaf(u21, c10, u20 * c00));
        float t21 = fmaf(u22, c21, fmaf(u21, c11, u20 * c01));
        float t22 = fmaf(u22, c22, fmaf(u21, c12, u20 * c02));
        u00 = t00; u01 = t01; u02 = t02;
        u10 = t10; u11 = t11; u12 = t12;
        u20 = t20; u21 = t21; u22 = t22;

        const float s = invf[i];
        H[0] = fmaf(u00, s, H[0]); H[1] = fmaf(u01, s, H[1]); H[2] = fmaf(u02, s, H[2]);
        H[3] = fmaf(u10, s, H[3]); H[4] = fmaf(u11, s, H[4]); H[5] = fmaf(u12, s, H[5]);
        H[6] = fmaf(u20, s, H[6]); H[7] = fmaf(u21, s, H[7]); H[8] = fmaf(u22, s, H[8]);
    }
}

// 4 items per thread:
//   in : 4 * 32 B = 128 B  -> 8x LDG.128 contiguous
//   out: 4 * 36 B = 144 B  -> 9x STG.128 contiguous (16B-aligned since 144 % 16 == 0)
__global__ __launch_bounds__(256)
void homography_expm_kernel(const float4* __restrict__ v4,
                            float4* __restrict__ o4,
                            const float* __restrict__ v,
                            float* __restrict__ o,
                            int n)
{
    const int t = blockIdx.x * blockDim.x + threadIdx.x;
    const long base = (long)t * 4;

    if (base + 4 <= n) {
        // ---- vector fast path ----
        float4 in[8];
        const float4* p = v4 + (long)t * 8;
#pragma unroll
        for (int i = 0; i < 8; i++) in[i] = p[i];

        __align__(16) float out[36];
#pragma unroll
        for (int j = 0; j < 4; j++) {
            float vv[8];
            vv[0] = in[2 * j].x; vv[1] = in[2 * j].y;
            vv[2] = in[2 * j].z; vv[3] = in[2 * j].w;
            vv[4] = in[2 * j + 1].x; vv[5] = in[2 * j + 1].y;
            vv[6] = in[2 * j + 1].z; vv[7] = in[2 * j + 1].w;
            expm3x3(vv, out + 9 * j);
        }

        float4* q = o4 + (long)t * 9;
        const float4* src = reinterpret_cast<const float4*>(out);
#pragma unroll
        for (int i = 0; i < 9; i++) q[i] = src[i];
    } else if (base < n) {
        // ---- scalar tail ----
        for (long j = base; j < n; j++) {
            float vv[8];
#pragma unroll
            for (int k = 0; k < 8; k++) vv[k] = v[j * 8 + k];
            float H[9];
            expm3x3(vv, H);
#pragma unroll
            for (int k = 0; k < 9; k++) o[j * 9 + k] = H[k];
        }
    }
}

extern "C" void kernel_launch(void* const* d_in, const int* in_sizes, int n_in,
                              void* d_out, int out_size)
{
    const float* v = (const float*)d_in[0];
    float* o = (float*)d_out;
    const int n = in_sizes[0] / 8;             // number of homographies
    const int nthreads = (n + 3) / 4;          // 4 items per thread
    const int block = 256;
    const int grid = (nthreads + block - 1) / block;
    homography_expm_kernel<<<grid, block>>>(
        (const float4*)v, (float4*)o, v, o, n);
}

// round 3
// speedup vs baseline: 1.3847x; 1.3847x over previous
#include <cuda_runtime.h>

// HomographyNet via Cayley-Hamilton.
// C = [ v4   v2   v0 ]      (traceless, sl(3))
//     [ v3  -v4-v5 v1 ]
//     [ v6   v7   v5 ]
// C^3 = p*C + q*I,  p = tr(C^2)/2,  q = det(C)
// => sum_{i=0..9} C^i/i! = a(p,q)*I + b(p,q)*C + c(p,q)*C^2
// with the fixed polynomials below (exact expansion of the degree-9 series).

__device__ __forceinline__ void expm3x3_ch(const float vv[8], float H[9]) {
    const float c00 = vv[4], c01 = vv[2], c02 = vv[0];
    const float c10 = vv[3], c11 = -vv[4] - vv[5], c12 = vv[1];
    const float c20 = vv[6], c21 = vv[7], c22 = vv[5];

    // D = C^2
    const float d00 = fmaf(c02, c20, fmaf(c01, c10, c00 * c00));
    const float d01 = fmaf(c02, c21, fmaf(c01, c11, c00 * c01));
    const float d02 = fmaf(c02, c22, fmaf(c01, c12, c00 * c02));
    const float d10 = fmaf(c12, c20, fmaf(c11, c10, c10 * c00));
    const float d11 = fmaf(c12, c21, fmaf(c11, c11, c10 * c01));
    const float d12 = fmaf(c12, c22, fmaf(c11, c12, c10 * c02));
    const float d20 = fmaf(c22, c20, fmaf(c21, c10, c20 * c00));
    const float d21 = fmaf(c22, c21, fmaf(c21, c11, c20 * c01));
    const float d22 = fmaf(c22, c22, fmaf(c21, c12, c20 * c02));

    // invariants
    const float p = 0.5f * (d00 + d11 + d22);          // tr(C^2)/2
    const float q = fmaf(c00, fmaf(c11, c22, -c12 * c21),
                   fmaf(-c01, fmaf(c10, c22, -c12 * c20),
                         c02 * fmaf(c10, c21, -c11 * c20)));  // det(C)

    // monomials
    const float p2  = p * p;
    const float q2  = q * q;
    const float pq  = p * q;
    const float p3  = p2 * p;
    const float p4  = p2 * p2;
    const float q3  = q * q2;
    const float p2q = p2 * q;
    const float pq2 = p * q2;
    const float p3q = p3 * q;

    // a = 1 + q/6 + pq/120 + q2/720 + p2q/5040 + pq2/20160 + (q3+p3q)/362880
    float a = 1.0f;
    a = fmaf(q,   1.0f / 6.0f,      a);
    a = fmaf(pq,  1.0f / 120.0f,    a);
    a = fmaf(q2,  1.0f / 720.0f,    a);
    a = fmaf(p2q, 1.0f / 5040.0f,   a);
    a = fmaf(pq2, 1.0f / 20160.0f,  a);
    a = fmaf(q3,  1.0f / 362880.0f, a);
    a = fmaf(p3q, 1.0f / 362880.0f, a);

    // b = 1 + p/6 + q/24 + p2/120 + pq/360 + q2/5040 + p3/5040
    //       + p2q/13440 + pq2/120960 + p4/362880
    float b = 1.0f;
    b = fmaf(p,   1.0f / 6.0f,      b);
    b = fmaf(q,   1.0f / 24.0f,     b);
    b = fmaf(p2,  1.0f / 120.0f,    b);
    b = fmaf(pq,  1.0f / 360.0f,    b);
    b = fmaf(q2,  1.0f / 5040.0f,   b);
    b = fmaf(p3,  1.0f / 5040.0f,   b);
    b = fmaf(p2q, 1.0f / 13440.0f,  b);
    b = fmaf(pq2, 1.0f / 120960.0f, b);
    b = fmaf(p4,  1.0f / 362880.0f, b);

    // c = 1/2 + p/24 + q/120 + p2/720 + pq/2520 + q2/40320 + p3/40320 + p2q/120960
    float c = 0.5f;
    c = fmaf(p,   1.0f / 24.0f,     c);
    c = fmaf(q,   1.0f / 120.0f,    c);
    c = fmaf(p2,  1.0f / 720.0f,    c);
    c = fmaf(pq,  1.0f / 2520.0f,   c);
    c = fmaf(q2,  1.0f / 40320.0f,  c);
    c = fmaf(p3,  1.0f / 40320.0f,  c);
    c = fmaf(p2q, 1.0f / 120960.0f, c);

    // H = a*I + b*C + c*C^2
    H[0] = fmaf(b, c00, fmaf(c, d00, a));
    H[1] = fmaf(b, c01, c * d01);
    H[2] = fmaf(b, c02, c * d02);
    H[3] = fmaf(b, c10, c * d10);
    H[4] = fmaf(b, c11, fmaf(c, d11, a));
    H[5] = fmaf(b, c12, c * d12);
    H[6] = fmaf(b, c20, c * d20);
    H[7] = fmaf(b, c21, c * d21);
    H[8] = fmaf(b, c22, fmaf(c, d22, a));
}

// 4 items per thread:
//   in : 4 * 32 B = 128 B  -> 8x LDG.128 contiguous (streaming)
//   out: 4 * 36 B = 144 B  -> 9x STG.128 contiguous (streaming)
__global__ __launch_bounds__(256)
void homography_expm_kernel(const float4* __restrict__ v4,
                            float4* __restrict__ o4,
                            const float* __restrict__ v,
                            float* __restrict__ o,
                            int n)
{
    const int t = blockIdx.x * blockDim.x + threadIdx.x;
    const long base = (long)t * 4;

    if (base + 4 <= n) {
        float4 in[8];
        const float4* p = v4 + (long)t * 8;
#pragma unroll
        for (int i = 0; i < 8; i++) in[i] = __ldcs(p + i);

        __align__(16) float out[36];
#pragma unroll
        for (int j = 0; j < 4; j++) {
            float vv[8];
            vv[0] = in[2 * j].x; vv[1] = in[2 * j].y;
            vv[2] = in[2 * j].z; vv[3] = in[2 * j].w;
            vv[4] = in[2 * j + 1].x; vv[5] = in[2 * j + 1].y;
            vv[6] = in[2 * j + 1].z; vv[7] = in[2 * j + 1].w;
            expm3x3_ch(vv, out + 9 * j);
        }

        float4* q = o4 + (long)t * 9;
        const float4* src = reinterpret_cast<const float4*>(out);
#pragma unroll
        for (int i = 0; i < 9; i++) __stcs(q + i, src[i]);
    } else if (base < n) {
        for (long j = base; j < n; j++) {
            float vv[8];
#pragma unroll
            for (int k = 0; k < 8; k++) vv[k] = v[j * 8 + k];
            float H[9];
            expm3x3_ch(vv, H);
#pragma unroll
            for (int k = 0; k < 9; k++) o[j * 9 + k] = H[k];
        }
    }
}

extern "C" void kernel_launch(void* const* d_in, const int* in_sizes, int n_in,
                              void* d_out, int out_size)
{
    const float* v = (const float*)d_in[0];
    float* o = (float*)d_out;
    const int n = in_sizes[0] / 8;
    const int nthreads = (n + 3) / 4;
    const int block = 256;
    const int grid = (nthreads + block - 1) / block;
    homography_expm_kernel<<<grid, block>>>(
        (const float4*)v, (float4*)o, v, o, n);
}

// round 5
// speedup vs baseline: 2.2476x; 1.6231x over previous
#include <cuda_runtime.h>

// HomographyNet via Cayley-Hamilton.
// C = [ v4   v2   v0 ]      (traceless, sl(3))
//     [ v3  -v4-v5 v1 ]
//     [ v6   v7   v5 ]
// C^3 = p*C + q*I,  p = tr(C^2)/2,  q = det(C)
// => sum_{i=0..9} C^i/i! = a(p,q)*I + b(p,q)*C + c(p,q)*C^2   (exact degree-9 expansion)

__device__ __forceinline__ void expm3x3_ch(const float vv[8], float H[9]) {
    const float c00 = vv[4], c01 = vv[2], c02 = vv[0];
    const float c10 = vv[3], c11 = -vv[4] - vv[5], c12 = vv[1];
    const float c20 = vv[6], c21 = vv[7], c22 = vv[5];

    // D = C^2
    const float d00 = fmaf(c02, c20, fmaf(c01, c10, c00 * c00));
    const float d01 = fmaf(c02, c21, fmaf(c01, c11, c00 * c01));
    const float d02 = fmaf(c02, c22, fmaf(c01, c12, c00 * c02));
    const float d10 = fmaf(c12, c20, fmaf(c11, c10, c10 * c00));
    const float d11 = fmaf(c12, c21, fmaf(c11, c11, c10 * c01));
    const float d12 = fmaf(c12, c22, fmaf(c11, c12, c10 * c02));
    const float d20 = fmaf(c22, c20, fmaf(c21, c10, c20 * c00));
    const float d21 = fmaf(c22, c21, fmaf(c21, c11, c20 * c01));
    const float d22 = fmaf(c22, c22, fmaf(c21, c12, c20 * c02));

    // invariants
    const float p = 0.5f * (d00 + d11 + d22);          // tr(C^2)/2
    const float q = fmaf(c00, fmaf(c11, c22, -c12 * c21),
                   fmaf(-c01, fmaf(c10, c22, -c12 * c20),
                         c02 * fmaf(c10, c21, -c11 * c20)));  // det(C)

    // monomials
    const float p2  = p * p;
    const float q2  = q * q;
    const float pq  = p * q;
    const float p3  = p2 * p;
    const float p4  = p2 * p2;
    const float q3  = q * q2;
    const float p2q = p2 * q;
    const float pq2 = p * q2;
    const float p3q = p3 * q;

    float a = 1.0f;
    a = fmaf(q,   1.0f / 6.0f,      a);
    a = fmaf(pq,  1.0f / 120.0f,    a);
    a = fmaf(q2,  1.0f / 720.0f,    a);
    a = fmaf(p2q, 1.0f / 5040.0f,   a);
    a = fmaf(pq2, 1.0f / 20160.0f,  a);
    a = fmaf(q3,  1.0f / 362880.0f, a);
    a = fmaf(p3q, 1.0f / 362880.0f, a);

    float b = 1.0f;
    b = fmaf(p,   1.0f / 6.0f,      b);
    b = fmaf(q,   1.0f / 24.0f,     b);
    b = fmaf(p2,  1.0f / 120.0f,    b);
    b = fmaf(pq,  1.0f / 360.0f,    b);
    b = fmaf(q2,  1.0f / 5040.0f,   b);
    b = fmaf(p3,  1.0f / 5040.0f,   b);
    b = fmaf(p2q, 1.0f / 13440.0f,  b);
    b = fmaf(pq2, 1.0f / 120960.0f, b);
    b = fmaf(p4,  1.0f / 362880.0f, b);

    float c = 0.5f;
    c = fmaf(p,   1.0f / 24.0f,     c);
    c = fmaf(q,   1.0f / 120.0f,    c);
    c = fmaf(p2,  1.0f / 720.0f,    c);
    c = fmaf(pq,  1.0f / 2520.0f,   c);
    c = fmaf(q2,  1.0f / 40320.0f,  c);
    c = fmaf(p3,  1.0f / 40320.0f,  c);
    c = fmaf(p2q, 1.0f / 120960.0f, c);

    // H = a*I + b*C + c*C^2
    H[0] = fmaf(b, c00, fmaf(c, d00, a));
    H[1] = fmaf(b, c01, c * d01);
    H[2] = fmaf(b, c02, c * d02);
    H[3] = fmaf(b, c10, c * d10);
    H[4] = fmaf(b, c11, fmaf(c, d11, a));
    H[5] = fmaf(b, c12, c * d12);
    H[6] = fmaf(b, c20, c * d20);
    H[7] = fmaf(b, c21, c * d21);
    H[8] = fmaf(b, c22, fmaf(c, d22, a));
}

// 1 item/thread, 256 threads/block.
// Loads : 2x LDG.128 at 32B thread-stride (8 fully-used lines per warp instr).
// Stores: H -> smem at stride-9 words (conflict-free), then block-coalesced
//         STG.128 copy of the 2304-float (576-float4) output slab.
__global__ __launch_bounds__(256)
void homography_expm_kernel(const float4* __restrict__ v4,
                            float4* __restrict__ o4,
                            float* __restrict__ o,
                            int n)
{
    __shared__ __align__(16) float s[256 * 9];

    const int tid = threadIdx.x;
    const int blockbase = blockIdx.x * 256;
    const int item = blockbase + tid;

    if (item < n) {
        const float4 a4 = __ldcs(v4 + (long)item * 2);
        const float4 b4 = __ldcs(v4 + (long)item * 2 + 1);
        float vv[8] = {a4.x, a4.y, a4.z, a4.w, b4.x, b4.y, b4.z, b4.w};
        float H[9];
        expm3x3_ch(vv, H);
#pragma unroll
        for (int k = 0; k < 9; k++) s[tid * 9 + k] = H[k];  // stride 9: conflict-free
    }
    __syncthreads();

    const int items = min(256, n - blockbase);
    if (items == 256) {
        // full block: 576 coalesced float4 stores
        const float4* sf = reinterpret_cast<const float4*>(s);
        float4* dst = o4 + (long)blockIdx.x * 576;
        __stcs(dst + tid,       sf[tid]);
        __stcs(dst + tid + 256, sf[tid + 256]);
        if (tid < 64) __stcs(dst + tid + 512, sf[tid + 512]);
    } else if (items > 0) {
        // tail block: scalar coalesced copy
        const int total = items * 9;
        float* dst = o + (long)blockbase * 9;
        for (int idx = tid; idx < total; idx += 256) dst[idx] = s[idx];
    }
}

extern "C" void kernel_launch(void* const* d_in, const int* in_sizes, int n_in,
                              void* d_out, int out_size)
{
    const float* v = (const float*)d_in[0];
    float* o = (float*)d_out;
    const int n = in_sizes[0] / 8;
    const int grid = (n + 255) / 256;
    homography_expm_kernel<<<grid, 256>>>(
        (const float4*)v, (float4*)o, o, n);
}